// round 11
// baseline (speedup 1.0000x reference)
#include <cuda_runtime.h>
#include <cstdint>

#define SEQ    2048
#define DMODEL 1024
#define NHEAD  16
#define HDIM   64
#define QKV_STRIDE (3 * DMODEL)

// Scratch (device-global: no runtime allocation allowed)
__device__ float g_qkv[SEQ * 3 * DMODEL];   // [S, 3*DIM]  q|k|v packed
__device__ float g_att[SEQ * DMODEL];       // attention output [S, DIM]

// ---------------------------------------------------------------------------
// tf32 helpers
// ---------------------------------------------------------------------------
__device__ __forceinline__ uint32_t f2tf32(float x) {
    uint32_t r;
    asm("cvt.rna.tf32.f32 %0, %1;" : "=r"(r) : "f"(x));
    return r;
}

__device__ __forceinline__ void split_tf32(float x, uint32_t& hi, uint32_t& lo) {
    hi = f2tf32(x);
    lo = f2tf32(x - __uint_as_float(hi));
}

__device__ __forceinline__ uint2 split2_tf32(float x) {
    uint2 r;
    split_tf32(x, r.x, r.y);
    return r;
}

__device__ __forceinline__ void mma_tf32(float* d, const uint32_t* a,
                                         const uint32_t* b) {
    asm("mma.sync.aligned.m16n8k8.row.col.f32.tf32.tf32.f32 "
        "{%0,%1,%2,%3}, {%4,%5,%6,%7}, {%8,%9}, {%0,%1,%2,%3};"
        : "+f"(d[0]), "+f"(d[1]), "+f"(d[2]), "+f"(d[3])
        : "r"(a[0]), "r"(a[1]), "r"(a[2]), "r"(a[3]),
          "r"(b[0]), "r"(b[1]));
}

// ---------------------------------------------------------------------------
// TF32 tensor-core GEMM v2 (NT): C[M,N] = A[M,K] @ B[N,K]^T + bias[N]
// BM=128, BN=64, BK=16, 256 threads = 8 warps (4 m-bands x 2 n-bands),
// warp tile 32x32 = 2x4 m16n8k8. Double-buffered smem: one __syncthreads per
// K-tile; next tile's global loads overlap compute. 2 CTAs/SM.
// ---------------------------------------------------------------------------
__global__ __launch_bounds__(256, 2)
void tf32_gemm_nt(const float* __restrict__ A, const float* __restrict__ B,
                  const float* __restrict__ bias, float* __restrict__ C,
                  int N, int K) {
    constexpr int BM = 128, BN = 64, BK = 16, LD = 20;
    __shared__ __align__(16) uint32_t As[2][BM][LD];
    __shared__ __align__(16) uint32_t Bs[2][BN][LD];

    const int t    = threadIdx.x;
    const int lane = t & 31;
    const int w    = t >> 5;
    const int wm   = w >> 1;       // 0..3 -> 32-row band
    const int wn   = w & 1;        // 0..1 -> 32-col band
    const int g    = lane >> 2;    // 0..7
    const int tg   = lane & 3;     // 0..3
    const int bm   = blockIdx.y * BM;
    const int bn   = blockIdx.x * BN;

    // Staging mapping: A = 2 float4/thread (rows lr, lr+64), B = 1 float4
    const int lr = t >> 2;            // 0..63
    const int lc = (t & 3) * 4;       // 0,4,8,12
    const float* Ag = A + (size_t)(bm + lr) * K + lc;
    const float* Bg = B + (size_t)(bn + lr) * K + lc;
    const size_t rowskip = (size_t)64 * K;

    float acc[2][4][4];
#pragma unroll
    for (int mt = 0; mt < 2; mt++)
#pragma unroll
        for (int nt = 0; nt < 4; nt++)
#pragma unroll
            for (int e = 0; e < 4; e++) acc[mt][nt][e] = 0.f;

    const int T = K / BK;
    float4 pa0, pa1, pb0;

    // prologue: tile 0 -> buf 0
    pa0 = *(const float4*)(Ag);
    pa1 = *(const float4*)(Ag + rowskip);
    pb0 = *(const float4*)(Bg);
    As[0][lr][lc + 0] = f2tf32(pa0.x); As[0][lr][lc + 1] = f2tf32(pa0.y);
    As[0][lr][lc + 2] = f2tf32(pa0.z); As[0][lr][lc + 3] = f2tf32(pa0.w);
    As[0][lr + 64][lc + 0] = f2tf32(pa1.x); As[0][lr + 64][lc + 1] = f2tf32(pa1.y);
    As[0][lr + 64][lc + 2] = f2tf32(pa1.z); As[0][lr + 64][lc + 3] = f2tf32(pa1.w);
    Bs[0][lr][lc + 0] = f2tf32(pb0.x); Bs[0][lr][lc + 1] = f2tf32(pb0.y);
    Bs[0][lr][lc + 2] = f2tf32(pb0.z); Bs[0][lr][lc + 3] = f2tf32(pb0.w);
    __syncthreads();
    // start load of tile 1
    if (T > 1) {
        pa0 = *(const float4*)(Ag + BK);
        pa1 = *(const float4*)(Ag + BK + rowskip);
        pb0 = *(const float4*)(Bg + BK);
    }

    for (int tt = 0; tt < T; tt++) {
        const int buf = tt & 1;
        // ---- compute from buf (overlaps the pending global loads) ----------
#pragma unroll
        for (int ks = 0; ks < BK; ks += 8) {
            uint32_t af[2][4], bf[4][2];
#pragma unroll
            for (int mt = 0; mt < 2; mt++) {
                int row = wm * 32 + mt * 16 + g;
                af[mt][0] = As[buf][row][ks + tg];
                af[mt][1] = As[buf][row + 8][ks + tg];
                af[mt][2] = As[buf][row][ks + tg + 4];
                af[mt][3] = As[buf][row + 8][ks + tg + 4];
            }
#pragma unroll
            for (int nt = 0; nt < 4; nt++) {
                int col = wn * 32 + nt * 8 + g;
                bf[nt][0] = Bs[buf][col][ks + tg];
                bf[nt][1] = Bs[buf][col][ks + tg + 4];
            }
#pragma unroll
            for (int mt = 0; mt < 2; mt++)
#pragma unroll
                for (int nt = 0; nt < 4; nt++)
                    mma_tf32(acc[mt][nt], af[mt], bf[nt]);
        }

        // ---- stage tile tt+1 into the other buffer -------------------------
        if (tt + 1 < T) {
            const int nb = buf ^ 1;
            As[nb][lr][lc + 0] = f2tf32(pa0.x); As[nb][lr][lc + 1] = f2tf32(pa0.y);
            As[nb][lr][lc + 2] = f2tf32(pa0.z); As[nb][lr][lc + 3] = f2tf32(pa0.w);
            As[nb][lr + 64][lc + 0] = f2tf32(pa1.x); As[nb][lr + 64][lc + 1] = f2tf32(pa1.y);
            As[nb][lr + 64][lc + 2] = f2tf32(pa1.z); As[nb][lr + 64][lc + 3] = f2tf32(pa1.w);
            Bs[nb][lr][lc + 0] = f2tf32(pb0.x); Bs[nb][lr][lc + 1] = f2tf32(pb0.y);
            Bs[nb][lr][lc + 2] = f2tf32(pb0.z); Bs[nb][lr][lc + 3] = f2tf32(pb0.w);
            __syncthreads();
            if (tt + 2 < T) {
                int k0 = (tt + 2) * BK;
                pa0 = *(const float4*)(Ag + k0);
                pa1 = *(const float4*)(Ag + k0 + rowskip);
                pb0 = *(const float4*)(Bg + k0);
            }
        }
    }

    // ---- epilogue -----------------------------------------------------------
#pragma unroll
    for (int nt = 0; nt < 4; nt++) {
        int col = bn + wn * 32 + nt * 8 + tg * 2;
        float b0 = bias[col], b1 = bias[col + 1];
#pragma unroll
        for (int mt = 0; mt < 2; mt++) {
            int row = bm + wm * 32 + mt * 16 + g;
            float2 v0 = make_float2(acc[mt][nt][0] + b0, acc[mt][nt][1] + b1);
            float2 v1 = make_float2(acc[mt][nt][2] + b0, acc[mt][nt][3] + b1);
            *(float2*)(C + (size_t)row * N + col)       = v0;
            *(float2*)(C + (size_t)(row + 8) * N + col) = v1;
        }
    }
}

// ---------------------------------------------------------------------------
// RoPE applied in-place to q and k portions of g_qkv.
// ---------------------------------------------------------------------------
__global__ __launch_bounds__(256)
void rope_kernel(float* __restrict__ qkv, const float* __restrict__ sinp,
                 const float* __restrict__ cosp) {
    int idx = blockIdx.x * blockDim.x + threadIdx.x;
    int d     = idx & 31;
    int h     = (idx >> 5) & (NHEAD - 1);
    int s     = (idx >> 9) & (SEQ - 1);
    int which = idx >> 20;            // 0 = q, 1 = k
    float* base = qkv + (size_t)s * QKV_STRIDE + which * DMODEL + h * HDIM;
    float x1 = base[d];
    float x2 = base[d + 32];
    float cs = cosp[s * HDIM + d];
    float sn = sinp[s * HDIM + d];
    base[d]      = x1 * cs - x2 * sn;
    base[d + 32] = x2 * cs + x1 * sn;
}

// ---------------------------------------------------------------------------
// Tensor-core flash attention, 3xTF32, hi/lo packed as uint2 (LDS.64 paths).
// Block = (head, 128 queries), 256 threads = 8 warps, warp owns 16 q rows.
// K-tile = 64 keys. K/V/P rows hold 64 uint2 elements; LD2 = 68 = 64 + 4 pad.
// Bounds audit: max K/V idx 63*68+63 = 4347 < 4352; max P idx 127*68+63 =
// 8699 < 8704; total smem 139,264 B. All uint4 stores 16B-aligned.
// Bank analysis (uint2 = 2 banks, LDS.64 in 16-lane phases):
//   score K reads: banks 8g+2tg  -> conflict-free
//   PV     V reads: banks 8tg+2g -> conflict-free
//   PV     P reads: banks 8g+2tg -> conflict-free
// ---------------------------------------------------------------------------
constexpr int FBQ = 128;
constexpr int FBK = 64;
constexpr int LD2 = 68;   // uint2 stride: 64 elements/row + 4 pad
constexpr int SMEM_FATC =
    (FBK * LD2 + FBK * LD2 + FBQ * LD2) * (int)sizeof(uint2);  // 139,264 B

__global__ __launch_bounds__(256, 1)
void flash_attn_tc(const float* __restrict__ qkv, float* __restrict__ att) {
    extern __shared__ __align__(16) uint2 su2[];
    uint2* Khl = su2;                 // [FBK][LD2]  row = key,   col = dim
    uint2* Vhl = Khl + FBK * LD2;     // [FBK][LD2]  row = key,   col = dim
    uint2* Phl = Vhl + FBK * LD2;     // [FBQ][LD2]  row = query, col = key

    const int h  = blockIdx.y;
    const int q0 = blockIdx.x * FBQ;
    const int t  = threadIdx.x;
    const int lane = t & 31;
    const int w  = t >> 5;
    const int g  = lane >> 2;
    const int tg = lane & 3;
    const int r0 = w * 16 + g;
    const int r1 = r0 + 8;

    // ---- Q fragments: load once, scale by 1/sqrt(64), split hi/lo ----------
    uint32_t qa_hi[8][4], qa_lo[8][4];
    {
        const float* qg = qkv + (size_t)q0 * QKV_STRIDE + h * HDIM;
        const float* q_r0 = qg + (size_t)r0 * QKV_STRIDE;
        const float* q_r1 = qg + (size_t)r1 * QKV_STRIDE;
#pragma unroll
        for (int kk = 0; kk < 8; kk++) {
            int c0 = kk * 8 + tg, c1 = c0 + 4;
            split_tf32(q_r0[c0] * 0.125f, qa_hi[kk][0], qa_lo[kk][0]);
            split_tf32(q_r1[c0] * 0.125f, qa_hi[kk][1], qa_lo[kk][1]);
            split_tf32(q_r0[c1] * 0.125f, qa_hi[kk][2], qa_lo[kk][2]);
            split_tf32(q_r1[c1] * 0.125f, qa_hi[kk][3], qa_lo[kk][3]);
        }
    }

    float m0 = -1e30f, m1 = -1e30f, l0 = 0.f, l1 = 0.f;
    float oacc[8][4];
#pragma unroll
    for (int nt = 0; nt < 8; nt++)
#pragma unroll
        for (int e = 0; e < 4; e++) oacc[nt][e] = 0.f;

    const float* kg = qkv + DMODEL + h * HDIM;
    const float* vg = qkv + 2 * DMODEL + h * HDIM;

    for (int kt = 0; kt < SEQ / FBK; kt++) {
        __syncthreads();   // previous tile fully consumed
        // ---- stage K,V tile: split at store, (hi,lo) packed, STS.128 -------
#pragma unroll
        for (int it = 0; it < 4; it++) {
            int li  = it * 256 + t;          // 1024 float4 per tensor
            int key = li >> 4;
            int d4  = (li & 15) * 4;         // element column 0..60
            size_t goff = (size_t)(kt * FBK + key) * QKV_STRIDE + d4;
            float4 kv = *(const float4*)(kg + goff);
            float4 vv = *(const float4*)(vg + goff);
            uint2 k0v = split2_tf32(kv.x), k1v = split2_tf32(kv.y);
            uint2 k2v = split2_tf32(kv.z), k3v = split2_tf32(kv.w);
            uint2 v0v = split2_tf32(vv.x), v1v = split2_tf32(vv.y);
            uint2 v2v = split2_tf32(vv.z), v3v = split2_tf32(vv.w);
            uint2* kp = Khl + key * LD2 + d4;
            uint2* vp = Vhl + key * LD2 + d4;
            *(uint4*)(kp)     = make_uint4(k0v.x, k0v.y, k1v.x, k1v.y);
            *(uint4*)(kp + 2) = make_uint4(k2v.x, k2v.y, k3v.x, k3v.y);
            *(uint4*)(vp)     = make_uint4(v0v.x, v0v.y, v1v.x, v1v.y);
            *(uint4*)(vp + 2) = make_uint4(v2v.x, v2v.y, v3v.x, v3v.y);
        }
        __syncthreads();

        // ---- S = (Q*scale) @ K^T  (3xTF32) ---------------------------------
        float sacc[8][4];
#pragma unroll
        for (int nt = 0; nt < 8; nt++)
#pragma unroll
            for (int e = 0; e < 4; e++) sacc[nt][e] = 0.f;

#pragma unroll
        for (int kk = 0; kk < 8; kk++) {
            int kc = kk * 8;
#pragma unroll
            for (int nt = 0; nt < 8; nt++) {
                int krow = nt * 8 + g;
                uint2 kf0 = Khl[krow * LD2 + kc + tg];       // LDS.64
                uint2 kf1 = Khl[krow * LD2 + kc + tg + 4];   // LDS.64
                uint32_t bh[2] = {kf0.x, kf1.x};
                uint32_t bl[2] = {kf0.y, kf1.y};
                mma_tf32(sacc[nt], qa_hi[kk], bh);
                mma_tf32(sacc[nt], qa_lo[kk], bh);
                mma_tf32(sacc[nt], qa_hi[kk], bl);
            }
        }

        // ---- online softmax -------------------------------------------------
        float mx0 = sacc[0][0], mx1 = sacc[0][2];
#pragma unroll
        for (int nt = 0; nt < 8; nt++) {
            mx0 = fmaxf(mx0, fmaxf(sacc[nt][0], sacc[nt][1]));
            mx1 = fmaxf(mx1, fmaxf(sacc[nt][2], sacc[nt][3]));
        }
        mx0 = fmaxf(mx0, __shfl_xor_sync(0xffffffffu, mx0, 1));
        mx0 = fmaxf(mx0, __shfl_xor_sync(0xffffffffu, mx0, 2));
        mx1 = fmaxf(mx1, __shfl_xor_sync(0xffffffffu, mx1, 1));
        mx1 = fmaxf(mx1, __shfl_xor_sync(0xffffffffu, mx1, 2));

        float nm0 = fmaxf(m0, mx0), nm1 = fmaxf(m1, mx1);
        float a0 = __expf(m0 - nm0), a1 = __expf(m1 - nm1);
        float s0 = 0.f, s1 = 0.f;
#pragma unroll
        for (int nt = 0; nt < 8; nt++) {
            int c = nt * 8 + 2 * tg;
            float p00 = __expf(sacc[nt][0] - nm0);
            float p01 = __expf(sacc[nt][1] - nm0);
            float p10 = __expf(sacc[nt][2] - nm1);
            float p11 = __expf(sacc[nt][3] - nm1);
            s0 += p00 + p01;
            s1 += p10 + p11;
            uint2 a = split2_tf32(p00), b = split2_tf32(p01);
            uint2 cc = split2_tf32(p10), d = split2_tf32(p11);
            *(uint4*)(Phl + r0 * LD2 + c) = make_uint4(a.x, a.y, b.x, b.y);
            *(uint4*)(Phl + r1 * LD2 + c) = make_uint4(cc.x, cc.y, d.x, d.y);
        }
        s0 += __shfl_xor_sync(0xffffffffu, s0, 1);
        s0 += __shfl_xor_sync(0xffffffffu, s0, 2);
        s1 += __shfl_xor_sync(0xffffffffu, s1, 1);
        s1 += __shfl_xor_sync(0xffffffffu, s1, 2);
        l0 = l0 * a0 + s0;
        l1 = l1 * a1 + s1;
        m0 = nm0; m1 = nm1;
#pragma unroll
        for (int nt = 0; nt < 8; nt++) {
            oacc[nt][0] *= a0; oacc[nt][1] *= a0;
            oacc[nt][2] *= a1; oacc[nt][3] *= a1;
        }
        __syncwarp();   // P region is per-warp-private

        // ---- O += P @ V  (3xTF32) ------------------------------------------
#pragma unroll
        for (int kk = 0; kk < 8; kk++) {
            int kc = kk * 8;
            uint2 p0 = Phl[r0 * LD2 + kc + tg];
            uint2 p1 = Phl[r1 * LD2 + kc + tg];
            uint2 p2 = Phl[r0 * LD2 + kc + tg + 4];
            uint2 p3 = Phl[r1 * LD2 + kc + tg + 4];
            uint32_t pah[4] = {p0.x, p1.x, p2.x, p3.x};
            uint32_t pal[4] = {p0.y, p1.y, p2.y, p3.y};
#pragma unroll
            for (int nt = 0; nt < 8; nt++) {
                int dcol = nt * 8 + g;
                uint2 vf0 = Vhl[(kc + tg) * LD2 + dcol];
                uint2 vf1 = Vhl[(kc + tg + 4) * LD2 + dcol];
                uint32_t bh[2] = {vf0.x, vf1.x};
                uint32_t bl[2] = {vf0.y, vf1.y};
                mma_tf32(oacc[nt], pah, bh);
                mma_tf32(oacc[nt], pal, bh);
                mma_tf32(oacc[nt], pah, bl);
            }
        }
    }

    // ---- epilogue -----------------------------------------------------------
    float inv0 = 1.f / l0, inv1 = 1.f / l1;
#pragma unroll
    for (int nt = 0; nt < 8; nt++) {
        int col = h * HDIM + nt * 8 + 2 * tg;
        *(float2*)(att + (size_t)(q0 + r0) * DMODEL + col) =
            make_float2(oacc[nt][0] * inv0, oacc[nt][1] * inv0);
        *(float2*)(att + (size_t)(q0 + r1) * DMODEL + col) =
            make_float2(oacc[nt][2] * inv1, oacc[nt][3] * inv1);
    }
}

// ---------------------------------------------------------------------------
extern "C" void kernel_launch(void* const* d_in, const int* in_sizes, int n_in,
                              void* d_out, int out_size) {
    const float* x     = (const float*)d_in[0];
    const float* sinp  = (const float*)d_in[1];
    const float* cosp  = (const float*)d_in[2];
    const float* Wqkv  = (const float*)d_in[3];
    const float* bqkv  = (const float*)d_in[4];
    const float* Wproj = (const float*)d_in[5];
    const float* bproj = (const float*)d_in[6];
    float* out = (float*)d_out;

    float* qkv = nullptr;
    float* att = nullptr;
    cudaGetSymbolAddress((void**)&qkv, g_qkv);
    cudaGetSymbolAddress((void**)&att, g_att);

    // 1) QKV = x @ Wqkv^T + b  (M=2048, N=3072, K=1024)
    {
        dim3 grid(3072 / 64, SEQ / 128);
        tf32_gemm_nt<<<grid, 256>>>(x, Wqkv, bqkv, qkv, 3072, DMODEL);
    }
    // 2) RoPE on q and k
    rope_kernel<<<(2 * SEQ * NHEAD * 32) / 256, 256>>>(qkv, sinp, cosp);

    // 3) Flash attention (tensor cores, 3xTF32, packed hi/lo)
    cudaFuncSetAttribute(flash_attn_tc, cudaFuncAttributeMaxDynamicSharedMemorySize,
                         SMEM_FATC);
    {
        dim3 grid(SEQ / FBQ, NHEAD);
        flash_attn_tc<<<grid, 256, SMEM_FATC>>>(qkv, att);
    }
    // 4) out = att @ Wproj^T + b  (M=2048, N=1024, K=1024)
    {
        dim3 grid(DMODEL / 64, SEQ / 128);
        tf32_gemm_nt<<<grid, 256>>>(att, Wproj, bproj, out, DMODEL, DMODEL);
    }
}

// round 12
// speedup vs baseline: 1.3041x; 1.3041x over previous
#include <cuda_runtime.h>
#include <cuda_bf16.h>
#include <cstdint>

#define SEQ    2048
#define DMODEL 1024
#define NHEAD  16
#define HDIM   64
#define QKV_STRIDE (3 * DMODEL)

// Scratch (device-global: no runtime allocation allowed)
__device__ float g_qkv[SEQ * 3 * DMODEL];   // [S, 3*DIM]  q|k|v packed
__device__ float g_att[SEQ * DMODEL];       // attention output [S, DIM]

// ---------------------------------------------------------------------------
// tf32 helpers (GEMM path, unchanged)
// ---------------------------------------------------------------------------
__device__ __forceinline__ uint32_t f2tf32(float x) {
    uint32_t r;
    asm("cvt.rna.tf32.f32 %0, %1;" : "=r"(r) : "f"(x));
    return r;
}

__device__ __forceinline__ void mma_tf32(float* d, const uint32_t* a,
                                         const uint32_t* b) {
    asm("mma.sync.aligned.m16n8k8.row.col.f32.tf32.tf32.f32 "
        "{%0,%1,%2,%3}, {%4,%5,%6,%7}, {%8,%9}, {%0,%1,%2,%3};"
        : "+f"(d[0]), "+f"(d[1]), "+f"(d[2]), "+f"(d[3])
        : "r"(a[0]), "r"(a[1]), "r"(a[2]), "r"(a[3]),
          "r"(b[0]), "r"(b[1]));
}

// ---------------------------------------------------------------------------
// bf16x2 helpers (flash path)
// pack: uint32 = (bf16(x) in low half, bf16(x - hi) in high half).
// A k16 mma over packed words with B duplicated (hi,hi)/(lo,lo) computes the
// exact product (hi+lo)(hi'+lo') in fp32 accumulation (~2^-17 rel error).
// ---------------------------------------------------------------------------
__device__ __forceinline__ uint32_t pack_bf16x2(float x) {
    __nv_bfloat16 h = __float2bfloat16(x);
    __nv_bfloat16 l = __float2bfloat16(x - __bfloat162float(h));
    return (uint32_t)__bfloat16_as_ushort(h) |
           ((uint32_t)__bfloat16_as_ushort(l) << 16);
}

__device__ __forceinline__ void mma_bf16(float* d, const uint32_t* a,
                                         const uint32_t* b) {
    asm("mma.sync.aligned.m16n8k16.row.col.f32.bf16.bf16.f32 "
        "{%0,%1,%2,%3}, {%4,%5,%6,%7}, {%8,%9}, {%0,%1,%2,%3};"
        : "+f"(d[0]), "+f"(d[1]), "+f"(d[2]), "+f"(d[3])
        : "r"(a[0]), "r"(a[1]), "r"(a[2]), "r"(a[3]),
          "r"(b[0]), "r"(b[1]));
}

// Duplicate low (hi) or high (lo) bf16 half into both halves.
__device__ __forceinline__ uint32_t dup_hi(uint32_t x) { return __byte_perm(x, x, 0x1010); }
__device__ __forceinline__ uint32_t dup_lo(uint32_t x) { return __byte_perm(x, x, 0x3232); }

// ---------------------------------------------------------------------------
// TF32 tensor-core GEMM (NT): C[M,N] = A[M,K] @ B[N,K]^T + bias[N]
// Unchanged from R9 (proj measured 61.4 us).
// ---------------------------------------------------------------------------
__global__ __launch_bounds__(256, 2)
void tf32_gemm_nt(const float* __restrict__ A, const float* __restrict__ B,
                  const float* __restrict__ bias, float* __restrict__ C,
                  int N, int K) {
    constexpr int BM = 128, BN = 64, BK = 16, LD = 20;
    __shared__ __align__(16) uint32_t As[2][BM][LD];
    __shared__ __align__(16) uint32_t Bs[2][BN][LD];

    const int t    = threadIdx.x;
    const int lane = t & 31;
    const int w    = t >> 5;
    const int wm   = w >> 1;
    const int wn   = w & 1;
    const int g    = lane >> 2;
    const int tg   = lane & 3;
    const int bm   = blockIdx.y * BM;
    const int bn   = blockIdx.x * BN;

    const int lr = t >> 2;
    const int lc = (t & 3) * 4;
    const float* Ag = A + (size_t)(bm + lr) * K + lc;
    const float* Bg = B + (size_t)(bn + lr) * K + lc;
    const size_t rowskip = (size_t)64 * K;

    float acc[2][4][4];
#pragma unroll
    for (int mt = 0; mt < 2; mt++)
#pragma unroll
        for (int nt = 0; nt < 4; nt++)
#pragma unroll
            for (int e = 0; e < 4; e++) acc[mt][nt][e] = 0.f;

    const int T = K / BK;
    float4 pa0, pa1, pb0;

    pa0 = *(const float4*)(Ag);
    pa1 = *(const float4*)(Ag + rowskip);
    pb0 = *(const float4*)(Bg);
    As[0][lr][lc + 0] = f2tf32(pa0.x); As[0][lr][lc + 1] = f2tf32(pa0.y);
    As[0][lr][lc + 2] = f2tf32(pa0.z); As[0][lr][lc + 3] = f2tf32(pa0.w);
    As[0][lr + 64][lc + 0] = f2tf32(pa1.x); As[0][lr + 64][lc + 1] = f2tf32(pa1.y);
    As[0][lr + 64][lc + 2] = f2tf32(pa1.z); As[0][lr + 64][lc + 3] = f2tf32(pa1.w);
    Bs[0][lr][lc + 0] = f2tf32(pb0.x); Bs[0][lr][lc + 1] = f2tf32(pb0.y);
    Bs[0][lr][lc + 2] = f2tf32(pb0.z); Bs[0][lr][lc + 3] = f2tf32(pb0.w);
    __syncthreads();
    if (T > 1) {
        pa0 = *(const float4*)(Ag + BK);
        pa1 = *(const float4*)(Ag + BK + rowskip);
        pb0 = *(const float4*)(Bg + BK);
    }

    for (int tt = 0; tt < T; tt++) {
        const int buf = tt & 1;
#pragma unroll
        for (int ks = 0; ks < BK; ks += 8) {
            uint32_t af[2][4], bf[4][2];
#pragma unroll
            for (int mt = 0; mt < 2; mt++) {
                int row = wm * 32 + mt * 16 + g;
                af[mt][0] = As[buf][row][ks + tg];
                af[mt][1] = As[buf][row + 8][ks + tg];
                af[mt][2] = As[buf][row][ks + tg + 4];
                af[mt][3] = As[buf][row + 8][ks + tg + 4];
            }
#pragma unroll
            for (int nt = 0; nt < 4; nt++) {
                int col = wn * 32 + nt * 8 + g;
                bf[nt][0] = Bs[buf][col][ks + tg];
                bf[nt][1] = Bs[buf][col][ks + tg + 4];
            }
#pragma unroll
            for (int mt = 0; mt < 2; mt++)
#pragma unroll
                for (int nt = 0; nt < 4; nt++)
                    mma_tf32(acc[mt][nt], af[mt], bf[nt]);
        }

        if (tt + 1 < T) {
            const int nb = buf ^ 1;
            As[nb][lr][lc + 0] = f2tf32(pa0.x); As[nb][lr][lc + 1] = f2tf32(pa0.y);
            As[nb][lr][lc + 2] = f2tf32(pa0.z); As[nb][lr][lc + 3] = f2tf32(pa0.w);
            As[nb][lr + 64][lc + 0] = f2tf32(pa1.x); As[nb][lr + 64][lc + 1] = f2tf32(pa1.y);
            As[nb][lr + 64][lc + 2] = f2tf32(pa1.z); As[nb][lr + 64][lc + 3] = f2tf32(pa1.w);
            Bs[nb][lr][lc + 0] = f2tf32(pb0.x); Bs[nb][lr][lc + 1] = f2tf32(pb0.y);
            Bs[nb][lr][lc + 2] = f2tf32(pb0.z); Bs[nb][lr][lc + 3] = f2tf32(pb0.w);
            __syncthreads();
            if (tt + 2 < T) {
                int k0 = (tt + 2) * BK;
                pa0 = *(const float4*)(Ag + k0);
                pa1 = *(const float4*)(Ag + k0 + rowskip);
                pb0 = *(const float4*)(Bg + k0);
            }
        }
    }

#pragma unroll
    for (int nt = 0; nt < 4; nt++) {
        int col = bn + wn * 32 + nt * 8 + tg * 2;
        float b0 = bias[col], b1 = bias[col + 1];
#pragma unroll
        for (int mt = 0; mt < 2; mt++) {
            int row = bm + wm * 32 + mt * 16 + g;
            float2 v0 = make_float2(acc[mt][nt][0] + b0, acc[mt][nt][1] + b1);
            float2 v1 = make_float2(acc[mt][nt][2] + b0, acc[mt][nt][3] + b1);
            *(float2*)(C + (size_t)row * N + col)       = v0;
            *(float2*)(C + (size_t)(row + 8) * N + col) = v1;
        }
    }
}

// ---------------------------------------------------------------------------
// RoPE applied in-place to q and k portions of g_qkv.
// ---------------------------------------------------------------------------
__global__ __launch_bounds__(256)
void rope_kernel(float* __restrict__ qkv, const float* __restrict__ sinp,
                 const float* __restrict__ cosp) {
    int idx = blockIdx.x * blockDim.x + threadIdx.x;
    int d     = idx & 31;
    int h     = (idx >> 5) & (NHEAD - 1);
    int s     = (idx >> 9) & (SEQ - 1);
    int which = idx >> 20;            // 0 = q, 1 = k
    float* base = qkv + (size_t)s * QKV_STRIDE + which * DMODEL + h * HDIM;
    float x1 = base[d];
    float x2 = base[d + 32];
    float cs = cosp[s * HDIM + d];
    float sn = sinp[s * HDIM + d];
    base[d]      = x1 * cs - x2 * sn;
    base[d + 32] = x2 * cs + x1 * sn;
}

// ---------------------------------------------------------------------------
// Flash attention v3: split-bf16 (bf16x2) tensor cores.
// Each fp32 element lives in smem as ONE uint32 (bf16 hi | bf16 lo<<16).
// m16n8k16 bf16 mma with B duplicated via PRMT:
//   mma(A=(hi,lo), B=(hi',hi')) + mma(A=(hi,lo), B=(lo',lo'))
//     = sum (hi+lo)(hi'+lo')  -- exact compensated product, fp32 accum.
// vs 3xTF32: smem bytes/element halved (4B), mma count -33%.
// Block = (head, 128 queries), 256 thr = 8 warps, warp owns 16 q rows.
// Strides: K/P = 68 (banks 4g+tg, conflict-free), V = 72 (banks 8tg+g).
// smem 70,656 B -> 2 CTAs/SM; grid 256 blocks -> <1 wave.
// ---------------------------------------------------------------------------
constexpr int FBQ = 128;
constexpr int FBK = 64;
constexpr int KLD = 68;   // uint32 stride for K and P rows (64 + 4 pad)
constexpr int VLD = 72;   // uint32 stride for V rows (64 + 8 pad)
constexpr int SMEM_FATC =
    (FBK * KLD + FBK * VLD + FBQ * KLD) * (int)sizeof(uint32_t);  // 70,656 B

__global__ __launch_bounds__(256, 2)
void flash_attn_tc(const float* __restrict__ qkv, float* __restrict__ att) {
    extern __shared__ __align__(16) uint32_t su[];
    uint32_t* Ks = su;                 // [FBK][KLD]  row = key,   col = dim
    uint32_t* Vs = Ks + FBK * KLD;     // [FBK][VLD]  row = key,   col = dim
    uint32_t* Ps = Vs + FBK * VLD;     // [FBQ][KLD]  row = query, col = key

    const int h  = blockIdx.y;
    const int q0 = blockIdx.x * FBQ;
    const int t  = threadIdx.x;
    const int lane = t & 31;
    const int w  = t >> 5;
    const int g  = lane >> 2;
    const int tg = lane & 3;
    const int r0 = w * 16 + g;
    const int r1 = r0 + 8;

    // ---- Q fragments: load once, scale by 1/sqrt(64), pack bf16x2 ----------
    uint32_t qa[8][4];
    {
        const float* qg = qkv + (size_t)q0 * QKV_STRIDE + h * HDIM;
        const float* q_r0 = qg + (size_t)r0 * QKV_STRIDE;
        const float* q_r1 = qg + (size_t)r1 * QKV_STRIDE;
#pragma unroll
        for (int kk = 0; kk < 8; kk++) {
            int c0 = kk * 8 + tg, c1 = c0 + 4;
            qa[kk][0] = pack_bf16x2(q_r0[c0] * 0.125f);
            qa[kk][1] = pack_bf16x2(q_r1[c0] * 0.125f);
            qa[kk][2] = pack_bf16x2(q_r0[c1] * 0.125f);
            qa[kk][3] = pack_bf16x2(q_r1[c1] * 0.125f);
        }
    }

    float m0 = -1e30f, m1 = -1e30f, l0 = 0.f, l1 = 0.f;
    float oacc[8][4];
#pragma unroll
    for (int nt = 0; nt < 8; nt++)
#pragma unroll
        for (int e = 0; e < 4; e++) oacc[nt][e] = 0.f;

    const float* kg = qkv + DMODEL + h * HDIM;
    const float* vg = qkv + 2 * DMODEL + h * HDIM;

    for (int kt = 0; kt < SEQ / FBK; kt++) {
        __syncthreads();   // previous tile fully consumed
        // ---- stage K,V tile: pack bf16x2 at store, STS.128 -----------------
#pragma unroll
        for (int it = 0; it < 4; it++) {
            int li  = it * 256 + t;          // 1024 float4 per tensor
            int key = li >> 4;
            int d4  = (li & 15) * 4;         // column 0..60
            size_t goff = (size_t)(kt * FBK + key) * QKV_STRIDE + d4;
            float4 kv = *(const float4*)(kg + goff);
            float4 vv = *(const float4*)(vg + goff);
            *(uint4*)(Ks + key * KLD + d4) =
                make_uint4(pack_bf16x2(kv.x), pack_bf16x2(kv.y),
                           pack_bf16x2(kv.z), pack_bf16x2(kv.w));
            *(uint4*)(Vs + key * VLD + d4) =
                make_uint4(pack_bf16x2(vv.x), pack_bf16x2(vv.y),
                           pack_bf16x2(vv.z), pack_bf16x2(vv.w));
        }
        __syncthreads();

        // ---- S = (Q*scale) @ K^T  (split-bf16, 2 mma per fragment) ---------
        float sacc[8][4];
#pragma unroll
        for (int nt = 0; nt < 8; nt++)
#pragma unroll
            for (int e = 0; e < 4; e++) sacc[nt][e] = 0.f;

#pragma unroll
        for (int kk = 0; kk < 8; kk++) {
            int kc = kk * 8;
#pragma unroll
            for (int nt = 0; nt < 8; nt++) {
                int krow = nt * 8 + g;
                uint32_t b0 = Ks[krow * KLD + kc + tg];
                uint32_t b1 = Ks[krow * KLD + kc + tg + 4];
                uint32_t bhh[2] = {dup_hi(b0), dup_hi(b1)};
                uint32_t bll[2] = {dup_lo(b0), dup_lo(b1)};
                mma_bf16(sacc[nt], qa[kk], bhh);
                mma_bf16(sacc[nt], qa[kk], bll);
            }
        }

        // ---- online softmax -------------------------------------------------
        float mx0 = sacc[0][0], mx1 = sacc[0][2];
#pragma unroll
        for (int nt = 0; nt < 8; nt++) {
            mx0 = fmaxf(mx0, fmaxf(sacc[nt][0], sacc[nt][1]));
            mx1 = fmaxf(mx1, fmaxf(sacc[nt][2], sacc[nt][3]));
        }
        mx0 = fmaxf(mx0, __shfl_xor_sync(0xffffffffu, mx0, 1));
        mx0 = fmaxf(mx0, __shfl_xor_sync(0xffffffffu, mx0, 2));
        mx1 = fmaxf(mx1, __shfl_xor_sync(0xffffffffu, mx1, 1));
        mx1 = fmaxf(mx1, __shfl_xor_sync(0xffffffffu, mx1, 2));

        float nm0 = fmaxf(m0, mx0), nm1 = fmaxf(m1, mx1);
        float a0 = __expf(m0 - nm0), a1 = __expf(m1 - nm1);
        float s0 = 0.f, s1 = 0.f;
#pragma unroll
        for (int nt = 0; nt < 8; nt++) {
            int c = nt * 8 + 2 * tg;
            float p00 = __expf(sacc[nt][0] - nm0);
            float p01 = __expf(sacc[nt][1] - nm0);
            float p10 = __expf(sacc[nt][2] - nm1);
            float p11 = __expf(sacc[nt][3] - nm1);
            s0 += p00 + p01;
            s1 += p10 + p11;
            *(uint2*)(Ps + r0 * KLD + c) =
                make_uint2(pack_bf16x2(p00), pack_bf16x2(p01));
            *(uint2*)(Ps + r1 * KLD + c) =
                make_uint2(pack_bf16x2(p10), pack_bf16x2(p11));
        }
        s0 += __shfl_xor_sync(0xffffffffu, s0, 1);
        s0 += __shfl_xor_sync(0xffffffffu, s0, 2);
        s1 += __shfl_xor_sync(0xffffffffu, s1, 1);
        s1 += __shfl_xor_sync(0xffffffffu, s1, 2);
        l0 = l0 * a0 + s0;
        l1 = l1 * a1 + s1;
        m0 = nm0; m1 = nm1;
#pragma unroll
        for (int nt = 0; nt < 8; nt++) {
            oacc[nt][0] *= a0; oacc[nt][1] *= a0;
            oacc[nt][2] *= a1; oacc[nt][3] *= a1;
        }
        __syncwarp();   // P region is per-warp-private

        // ---- O += P @ V  (split-bf16) --------------------------------------
#pragma unroll
        for (int kk = 0; kk < 8; kk++) {
            int kc = kk * 8;
            uint32_t pa[4];
            pa[0] = Ps[r0 * KLD + kc + tg];
            pa[1] = Ps[r1 * KLD + kc + tg];
            pa[2] = Ps[r0 * KLD + kc + tg + 4];
            pa[3] = Ps[r1 * KLD + kc + tg + 4];
#pragma unroll
            for (int nt = 0; nt < 8; nt++) {
                int dcol = nt * 8 + g;
                uint32_t v0 = Vs[(kc + tg) * VLD + dcol];
                uint32_t v1 = Vs[(kc + tg + 4) * VLD + dcol];
                uint32_t bhh[2] = {dup_hi(v0), dup_hi(v1)};
                uint32_t bll[2] = {dup_lo(v0), dup_lo(v1)};
                mma_bf16(oacc[nt], pa, bhh);
                mma_bf16(oacc[nt], pa, bll);
            }
        }
    }

    // ---- epilogue -----------------------------------------------------------
    float inv0 = 1.f / l0, inv1 = 1.f / l1;
#pragma unroll
    for (int nt = 0; nt < 8; nt++) {
        int col = h * HDIM + nt * 8 + 2 * tg;
        *(float2*)(att + (size_t)(q0 + r0) * DMODEL + col) =
            make_float2(oacc[nt][0] * inv0, oacc[nt][1] * inv0);
        *(float2*)(att + (size_t)(q0 + r1) * DMODEL + col) =
            make_float2(oacc[nt][2] * inv1, oacc[nt][3] * inv1);
    }
}

// ---------------------------------------------------------------------------
extern "C" void kernel_launch(void* const* d_in, const int* in_sizes, int n_in,
                              void* d_out, int out_size) {
    const float* x     = (const float*)d_in[0];
    const float* sinp  = (const float*)d_in[1];
    const float* cosp  = (const float*)d_in[2];
    const float* Wqkv  = (const float*)d_in[3];
    const float* bqkv  = (const float*)d_in[4];
    const float* Wproj = (const float*)d_in[5];
    const float* bproj = (const float*)d_in[6];
    float* out = (float*)d_out;

    float* qkv = nullptr;
    float* att = nullptr;
    cudaGetSymbolAddress((void**)&qkv, g_qkv);
    cudaGetSymbolAddress((void**)&att, g_att);

    // 1) QKV = x @ Wqkv^T + b  (M=2048, N=3072, K=1024)
    {
        dim3 grid(3072 / 64, SEQ / 128);
        tf32_gemm_nt<<<grid, 256>>>(x, Wqkv, bqkv, qkv, 3072, DMODEL);
    }
    // 2) RoPE on q and k
    rope_kernel<<<(2 * SEQ * NHEAD * 32) / 256, 256>>>(qkv, sinp, cosp);

    // 3) Flash attention (split-bf16 tensor cores, 2 CTAs/SM)
    cudaFuncSetAttribute(flash_attn_tc, cudaFuncAttributeMaxDynamicSharedMemorySize,
                         SMEM_FATC);
    {
        dim3 grid(SEQ / FBQ, NHEAD);
        flash_attn_tc<<<grid, 256, SMEM_FATC>>>(qkv, att);
    }
    // 4) out = att @ Wproj^T + b  (M=2048, N=1024, K=1024)
    {
        dim3 grid(DMODEL / 64, SEQ / 128);
        tf32_gemm_nt<<<grid, 256>>>(att, Wproj, bproj, out, DMODEL, DMODEL);
    }
}

// round 16
// speedup vs baseline: 1.3415x; 1.0287x over previous
#include <cuda_runtime.h>
#include <cuda_bf16.h>
#include <cstdint>

#define SEQ    2048
#define DMODEL 1024
#define NHEAD  16
#define HDIM   64
#define QKV_STRIDE (3 * DMODEL)

// Scratch (device-global: no runtime allocation allowed)
__device__ float    g_qkv[SEQ * 3 * DMODEL];    // fp32 q|k|v (GEMM output)
__device__ uint32_t g_qkvp[SEQ * 3 * DMODEL];   // packed bf16x2 (roped q,k + v)
__device__ float    g_att[SEQ * DMODEL];        // attention output [S, DIM]

// ---------------------------------------------------------------------------
// tf32 helpers (GEMM path)
// ---------------------------------------------------------------------------
__device__ __forceinline__ uint32_t f2tf32(float x) {
    uint32_t r;
    asm("cvt.rna.tf32.f32 %0, %1;" : "=r"(r) : "f"(x));
    return r;
}

__device__ __forceinline__ void mma_tf32(float* d, const uint32_t* a,
                                         const uint32_t* b) {
    asm("mma.sync.aligned.m16n8k8.row.col.f32.tf32.tf32.f32 "
        "{%0,%1,%2,%3}, {%4,%5,%6,%7}, {%8,%9}, {%0,%1,%2,%3};"
        : "+f"(d[0]), "+f"(d[1]), "+f"(d[2]), "+f"(d[3])
        : "r"(a[0]), "r"(a[1]), "r"(a[2]), "r"(a[3]),
          "r"(b[0]), "r"(b[1]));
}

// ---------------------------------------------------------------------------
// bf16x2 helpers (flash path): uint32 = (bf16 hi | bf16(x-hi) << 16).
// mma(A=(hi,lo), B=(hi',hi')) + mma(A, B=(lo',lo')) = exact (hi+lo)(hi'+lo').
// ---------------------------------------------------------------------------
__device__ __forceinline__ uint32_t pack_bf16x2(float x) {
    __nv_bfloat16 h = __float2bfloat16(x);
    __nv_bfloat16 l = __float2bfloat16(x - __bfloat162float(h));
    return (uint32_t)__bfloat16_as_ushort(h) |
           ((uint32_t)__bfloat16_as_ushort(l) << 16);
}
__device__ __forceinline__ uint32_t dup_hi(uint32_t x) { return __byte_perm(x, x, 0x1010); }
__device__ __forceinline__ uint32_t dup_lo(uint32_t x) { return __byte_perm(x, x, 0x3232); }

__device__ __forceinline__ void mma_bf16(float* d, const uint32_t* a,
                                         const uint32_t* b) {
    asm("mma.sync.aligned.m16n8k16.row.col.f32.bf16.bf16.f32 "
        "{%0,%1,%2,%3}, {%4,%5,%6,%7}, {%8,%9}, {%0,%1,%2,%3};"
        : "+f"(d[0]), "+f"(d[1]), "+f"(d[2]), "+f"(d[3])
        : "r"(a[0]), "r"(a[1]), "r"(a[2]), "r"(a[3]),
          "r"(b[0]), "r"(b[1]));
}

// Scale a packed (hi,lo) pair by an exact power of two (0.125): exponent
// shift only, so hi' = hi/8 and lo' = lo/8 remain the exact split of x/8.
__device__ __forceinline__ uint32_t scale8_packed(uint32_t w) {
    __nv_bfloat162 b = *reinterpret_cast<__nv_bfloat162*>(&w);
    __nv_bfloat162 s = __float2bfloat162_rn(0.125f);
    b = __hmul2(b, s);
    return *reinterpret_cast<uint32_t*>(&b);
}

// ---------------------------------------------------------------------------
// TF32 tensor-core GEMM v3 (NT): C[M,N] = A[M,K] @ B[N,K]^T + bias[N]
// BM=128, BN=128, BK=16, 256 threads = 8 warps (2 m-bands x 4 n-bands),
// warp tile 64x32 = 4x4 m16n8k8 (16 mma / 24 LDS per k8-step = 1.5 LDS/mma,
// down from 2.0 in the 32x32-warp version). Double-buffered smem, one
// __syncthreads per K-tile. Fragment banks (20g+tg) mod 32: conflict-free.
// ---------------------------------------------------------------------------
__global__ __launch_bounds__(256, 2)
void tf32_gemm_nt(const float* __restrict__ A, const float* __restrict__ B,
                  const float* __restrict__ bias, float* __restrict__ C,
                  int N, int K) {
    constexpr int BM = 128, BN = 128, BK = 16, LD = 20;
    __shared__ __align__(16) uint32_t As[2][BM][LD];
    __shared__ __align__(16) uint32_t Bs[2][BN][LD];

    const int t    = threadIdx.x;
    const int lane = t & 31;
    const int w    = t >> 5;
    const int wm   = w >> 2;       // 0..1 -> 64-row band
    const int wn   = w & 3;        // 0..3 -> 32-col band
    const int g    = lane >> 2;    // 0..7
    const int tg   = lane & 3;     // 0..3
    const int bm   = blockIdx.y * BM;
    const int bn   = blockIdx.x * BN;

    // Staging: 128 rows x 16 k = 512 float4 per tensor; 2 float4/thread.
    const int lr = t >> 1;            // row 0..127
    const int lc = (t & 1) * 8;       // k offset 0 or 8
    const float* Ag = A + (size_t)(bm + lr) * K + lc;
    const float* Bg = B + (size_t)(bn + lr) * K + lc;

    float acc[4][4][4];
#pragma unroll
    for (int mt = 0; mt < 4; mt++)
#pragma unroll
        for (int nt = 0; nt < 4; nt++)
#pragma unroll
            for (int e = 0; e < 4; e++) acc[mt][nt][e] = 0.f;

    const int T = K / BK;
    float4 pa0, pa1, pb0, pb1;

    // prologue: tile 0 -> buf 0
    pa0 = *(const float4*)(Ag);
    pa1 = *(const float4*)(Ag + 4);
    pb0 = *(const float4*)(Bg);
    pb1 = *(const float4*)(Bg + 4);
    As[0][lr][lc + 0] = f2tf32(pa0.x); As[0][lr][lc + 1] = f2tf32(pa0.y);
    As[0][lr][lc + 2] = f2tf32(pa0.z); As[0][lr][lc + 3] = f2tf32(pa0.w);
    As[0][lr][lc + 4] = f2tf32(pa1.x); As[0][lr][lc + 5] = f2tf32(pa1.y);
    As[0][lr][lc + 6] = f2tf32(pa1.z); As[0][lr][lc + 7] = f2tf32(pa1.w);
    Bs[0][lr][lc + 0] = f2tf32(pb0.x); Bs[0][lr][lc + 1] = f2tf32(pb0.y);
    Bs[0][lr][lc + 2] = f2tf32(pb0.z); Bs[0][lr][lc + 3] = f2tf32(pb0.w);
    Bs[0][lr][lc + 4] = f2tf32(pb1.x); Bs[0][lr][lc + 5] = f2tf32(pb1.y);
    Bs[0][lr][lc + 6] = f2tf32(pb1.z); Bs[0][lr][lc + 7] = f2tf32(pb1.w);
    __syncthreads();
    if (T > 1) {
        pa0 = *(const float4*)(Ag + BK);
        pa1 = *(const float4*)(Ag + BK + 4);
        pb0 = *(const float4*)(Bg + BK);
        pb1 = *(const float4*)(Bg + BK + 4);
    }

    for (int tt = 0; tt < T; tt++) {
        const int buf = tt & 1;
        // ---- compute from buf ----------------------------------------------
#pragma unroll
        for (int ks = 0; ks < BK; ks += 8) {
            uint32_t af[4][4], bf[4][2];
#pragma unroll
            for (int mt = 0; mt < 4; mt++) {
                int row = wm * 64 + mt * 16 + g;
                af[mt][0] = As[buf][row][ks + tg];
                af[mt][1] = As[buf][row + 8][ks + tg];
                af[mt][2] = As[buf][row][ks + tg + 4];
                af[mt][3] = As[buf][row + 8][ks + tg + 4];
            }
#pragma unroll
            for (int nt = 0; nt < 4; nt++) {
                int col = wn * 32 + nt * 8 + g;
                bf[nt][0] = Bs[buf][col][ks + tg];
                bf[nt][1] = Bs[buf][col][ks + tg + 4];
            }
#pragma unroll
            for (int mt = 0; mt < 4; mt++)
#pragma unroll
                for (int nt = 0; nt < 4; nt++)
                    mma_tf32(acc[mt][nt], af[mt], bf[nt]);
        }

        // ---- stage tile tt+1 into the other buffer -------------------------
        if (tt + 1 < T) {
            const int nb = buf ^ 1;
            As[nb][lr][lc + 0] = f2tf32(pa0.x); As[nb][lr][lc + 1] = f2tf32(pa0.y);
            As[nb][lr][lc + 2] = f2tf32(pa0.z); As[nb][lr][lc + 3] = f2tf32(pa0.w);
            As[nb][lr][lc + 4] = f2tf32(pa1.x); As[nb][lr][lc + 5] = f2tf32(pa1.y);
            As[nb][lr][lc + 6] = f2tf32(pa1.z); As[nb][lr][lc + 7] = f2tf32(pa1.w);
            Bs[nb][lr][lc + 0] = f2tf32(pb0.x); Bs[nb][lr][lc + 1] = f2tf32(pb0.y);
            Bs[nb][lr][lc + 2] = f2tf32(pb0.z); Bs[nb][lr][lc + 3] = f2tf32(pb0.w);
            Bs[nb][lr][lc + 4] = f2tf32(pb1.x); Bs[nb][lr][lc + 5] = f2tf32(pb1.y);
            Bs[nb][lr][lc + 6] = f2tf32(pb1.z); Bs[nb][lr][lc + 7] = f2tf32(pb1.w);
            __syncthreads();
            if (tt + 2 < T) {
                int k0 = (tt + 2) * BK;
                pa0 = *(const float4*)(Ag + k0);
                pa1 = *(const float4*)(Ag + k0 + 4);
                pb0 = *(const float4*)(Bg + k0);
                pb1 = *(const float4*)(Bg + k0 + 4);
            }
        }
    }

    // ---- epilogue -----------------------------------------------------------
#pragma unroll
    for (int nt = 0; nt < 4; nt++) {
        int col = bn + wn * 32 + nt * 8 + tg * 2;
        float b0 = bias[col], b1 = bias[col + 1];
#pragma unroll
        for (int mt = 0; mt < 4; mt++) {
            int row = bm + wm * 64 + mt * 16 + g;
            float2 v0 = make_float2(acc[mt][nt][0] + b0, acc[mt][nt][1] + b1);
            float2 v1 = make_float2(acc[mt][nt][2] + b0, acc[mt][nt][3] + b1);
            *(float2*)(C + (size_t)row * N + col)       = v0;
            *(float2*)(C + (size_t)(row + 8) * N + col) = v1;
        }
    }
}

// ---------------------------------------------------------------------------
// RoPE + pack: reads fp32 g_qkv, writes packed bf16x2 g_qkvp.
// which = 0 (q, roped), 1 (k, roped), 2 (v, pass-through pack).
// ---------------------------------------------------------------------------
__global__ __launch_bounds__(256)
void rope_pack_kernel(const float* __restrict__ qkv, uint32_t* __restrict__ qkvp,
                      const float* __restrict__ sinp, const float* __restrict__ cosp) {
    int idx = blockIdx.x * blockDim.x + threadIdx.x;   // 3 * 2048 * 512 total
    int d     = idx & 31;
    int h     = (idx >> 5) & (NHEAD - 1);
    int s     = (idx >> 9) & (SEQ - 1);
    int which = idx >> 20;            // 0 = q, 1 = k, 2 = v
    size_t base = (size_t)s * QKV_STRIDE + which * DMODEL + h * HDIM;
    float x1 = qkv[base + d];
    float x2 = qkv[base + d + 32];
    if (which < 2) {
        float cs = cosp[s * HDIM + d];
        float sn = sinp[s * HDIM + d];
        float y1 = x1 * cs - x2 * sn;
        float y2 = x2 * cs + x1 * sn;
        x1 = y1; x2 = y2;
    }
    qkvp[base + d]      = pack_bf16x2(x1);
    qkvp[base + d + 32] = pack_bf16x2(x2);
}

// ---------------------------------------------------------------------------
// Flash attention v3.1: split-bf16 mma.sync reading PRE-PACKED qkv.
// Staging is now a pure uint4 copy (no per-CTA re-packing); Q fragments load
// packed words and scale by the exact power-of-two 0.125 via one HMUL2.
// Everything else identical to the 492us R12 kernel.
// ---------------------------------------------------------------------------
constexpr int FBQ = 128;
constexpr int FBK = 64;
constexpr int KLD = 68;
constexpr int VLD = 72;
constexpr int SMEM_FATC =
    (FBK * KLD + FBK * VLD + FBQ * KLD) * (int)sizeof(uint32_t);  // 70,656 B

__global__ __launch_bounds__(256, 2)
void flash_attn_tc(const uint32_t* __restrict__ qkvp, float* __restrict__ att) {
    extern __shared__ __align__(16) uint32_t su[];
    uint32_t* Ks = su;
    uint32_t* Vs = Ks + FBK * KLD;
    uint32_t* Ps = Vs + FBK * VLD;

    const int h  = blockIdx.y;
    const int q0 = blockIdx.x * FBQ;
    const int t  = threadIdx.x;
    const int lane = t & 31;
    const int w  = t >> 5;
    const int g  = lane >> 2;
    const int tg = lane & 3;
    const int r0 = w * 16 + g;
    const int r1 = r0 + 8;

    // ---- Q fragments: packed loads + exact /8 scale -------------------------
    uint32_t qa[8][4];
    {
        const uint32_t* qg = qkvp + (size_t)q0 * QKV_STRIDE + h * HDIM;
        const uint32_t* q_r0 = qg + (size_t)r0 * QKV_STRIDE;
        const uint32_t* q_r1 = qg + (size_t)r1 * QKV_STRIDE;
#pragma unroll
        for (int kk = 0; kk < 8; kk++) {
            int c0 = kk * 8 + tg, c1 = c0 + 4;
            qa[kk][0] = scale8_packed(q_r0[c0]);
            qa[kk][1] = scale8_packed(q_r1[c0]);
            qa[kk][2] = scale8_packed(q_r0[c1]);
            qa[kk][3] = scale8_packed(q_r1[c1]);
        }
    }

    float m0 = -1e30f, m1 = -1e30f, l0 = 0.f, l1 = 0.f;
    float oacc[8][4];
#pragma unroll
    for (int nt = 0; nt < 8; nt++)
#pragma unroll
        for (int e = 0; e < 4; e++) oacc[nt][e] = 0.f;

    const uint32_t* kg = qkvp + DMODEL + h * HDIM;
    const uint32_t* vg = qkvp + 2 * DMODEL + h * HDIM;

    for (int kt = 0; kt < SEQ / FBK; kt++) {
        __syncthreads();
        // ---- stage K,V tile: pure uint4 copies ------------------------------
#pragma unroll
        for (int it = 0; it < 4; it++) {
            int li  = it * 256 + t;
            int key = li >> 4;
            int d4  = (li & 15) * 4;
            size_t goff = (size_t)(kt * FBK + key) * QKV_STRIDE + d4;
            uint4 kv = *(const uint4*)(kg + goff);
            uint4 vv = *(const uint4*)(vg + goff);
            *(uint4*)(Ks + key * KLD + d4) = kv;
            *(uint4*)(Vs + key * VLD + d4) = vv;
        }
        __syncthreads();

        // ---- S = (Q/8) @ K^T (split-bf16, 2 mma per fragment) ---------------
        float sacc[8][4];
#pragma unroll
        for (int nt = 0; nt < 8; nt++)
#pragma unroll
            for (int e = 0; e < 4; e++) sacc[nt][e] = 0.f;

#pragma unroll
        for (int kk = 0; kk < 8; kk++) {
            int kc = kk * 8;
#pragma unroll
            for (int nt = 0; nt < 8; nt++) {
                int krow = nt * 8 + g;
                uint32_t b0 = Ks[krow * KLD + kc + tg];
                uint32_t b1 = Ks[krow * KLD + kc + tg + 4];
                uint32_t bhh[2] = {dup_hi(b0), dup_hi(b1)};
                uint32_t bll[2] = {dup_lo(b0), dup_lo(b1)};
                mma_bf16(sacc[nt], qa[kk], bhh);
                mma_bf16(sacc[nt], qa[kk], bll);
            }
        }

        // ---- online softmax -------------------------------------------------
        float mx0 = sacc[0][0], mx1 = sacc[0][2];
#pragma unroll
        for (int nt = 0; nt < 8; nt++) {
            mx0 = fmaxf(mx0, fmaxf(sacc[nt][0], sacc[nt][1]));
            mx1 = fmaxf(mx1, fmaxf(sacc[nt][2], sacc[nt][3]));
        }
        mx0 = fmaxf(mx0, __shfl_xor_sync(0xffffffffu, mx0, 1));
        mx0 = fmaxf(mx0, __shfl_xor_sync(0xffffffffu, mx0, 2));
        mx1 = fmaxf(mx1, __shfl_xor_sync(0xffffffffu, mx1, 1));
        mx1 = fmaxf(mx1, __shfl_xor_sync(0xffffffffu, mx1, 2));

        float nm0 = fmaxf(m0, mx0), nm1 = fmaxf(m1, mx1);
        float a0 = __expf(m0 - nm0), a1 = __expf(m1 - nm1);
        float s0 = 0.f, s1 = 0.f;
#pragma unroll
        for (int nt = 0; nt < 8; nt++) {
            int c = nt * 8 + 2 * tg;
            float p00 = __expf(sacc[nt][0] - nm0);
            float p01 = __expf(sacc[nt][1] - nm0);
            float p10 = __expf(sacc[nt][2] - nm1);
            float p11 = __expf(sacc[nt][3] - nm1);
            s0 += p00 + p01;
            s1 += p10 + p11;
            *(uint2*)(Ps + r0 * KLD + c) =
                make_uint2(pack_bf16x2(p00), pack_bf16x2(p01));
            *(uint2*)(Ps + r1 * KLD + c) =
                make_uint2(pack_bf16x2(p10), pack_bf16x2(p11));
        }
        s0 += __shfl_xor_sync(0xffffffffu, s0, 1);
        s0 += __shfl_xor_sync(0xffffffffu, s0, 2);
        s1 += __shfl_xor_sync(0xffffffffu, s1, 1);
        s1 += __shfl_xor_sync(0xffffffffu, s1, 2);
        l0 = l0 * a0 + s0;
        l1 = l1 * a1 + s1;
        m0 = nm0; m1 = nm1;
#pragma unroll
        for (int nt = 0; nt < 8; nt++) {
            oacc[nt][0] *= a0; oacc[nt][1] *= a0;
            oacc[nt][2] *= a1; oacc[nt][3] *= a1;
        }
        __syncwarp();   // P region is per-warp-private

        // ---- O += P @ V (split-bf16) ----------------------------------------
#pragma unroll
        for (int kk = 0; kk < 8; kk++) {
            int kc = kk * 8;
            uint32_t pa[4];
            pa[0] = Ps[r0 * KLD + kc + tg];
            pa[1] = Ps[r1 * KLD + kc + tg];
            pa[2] = Ps[r0 * KLD + kc + tg + 4];
            pa[3] = Ps[r1 * KLD + kc + tg + 4];
#pragma unroll
            for (int nt = 0; nt < 8; nt++) {
                int dcol = nt * 8 + g;
                uint32_t v0 = Vs[(kc + tg) * VLD + dcol];
                uint32_t v1 = Vs[(kc + tg + 4) * VLD + dcol];
                uint32_t bhh[2] = {dup_hi(v0), dup_hi(v1)};
                uint32_t bll[2] = {dup_lo(v0), dup_lo(v1)};
                mma_bf16(oacc[nt], pa, bhh);
                mma_bf16(oacc[nt], pa, bll);
            }
        }
    }

    float inv0 = 1.f / l0, inv1 = 1.f / l1;
#pragma unroll
    for (int nt = 0; nt < 8; nt++) {
        int col = h * HDIM + nt * 8 + 2 * tg;
        *(float2*)(att + (size_t)(q0 + r0) * DMODEL + col) =
            make_float2(oacc[nt][0] * inv0, oacc[nt][1] * inv0);
        *(float2*)(att + (size_t)(q0 + r1) * DMODEL + col) =
            make_float2(oacc[nt][2] * inv1, oacc[nt][3] * inv1);
    }
}

// ---------------------------------------------------------------------------
extern "C" void kernel_launch(void* const* d_in, const int* in_sizes, int n_in,
                              void* d_out, int out_size) {
    const float* x     = (const float*)d_in[0];
    const float* sinp  = (const float*)d_in[1];
    const float* cosp  = (const float*)d_in[2];
    const float* Wqkv  = (const float*)d_in[3];
    const float* bqkv  = (const float*)d_in[4];
    const float* Wproj = (const float*)d_in[5];
    const float* bproj = (const float*)d_in[6];
    float* out = (float*)d_out;

    float* qkv = nullptr;
    uint32_t* qkvp = nullptr;
    float* att = nullptr;
    cudaGetSymbolAddress((void**)&qkv, g_qkv);
    cudaGetSymbolAddress((void**)&qkvp, g_qkvp);
    cudaGetSymbolAddress((void**)&att, g_att);

    cudaFuncSetAttribute(flash_attn_tc, cudaFuncAttributeMaxDynamicSharedMemorySize,
                         SMEM_FATC);

    // 1) QKV = x @ Wqkv^T + b  (M=2048, N=3072, K=1024) — tf32 v3
    {
        dim3 grid(3072 / 128, SEQ / 128);
        tf32_gemm_nt<<<grid, 256>>>(x, Wqkv, bqkv, qkv, 3072, DMODEL);
    }
    // 2) RoPE q,k + pack q,k,v into g_qkvp  (3 * 2048 * 512 threads)
    rope_pack_kernel<<<(3 * SEQ * NHEAD * 32) / 256, 256>>>(qkv, qkvp, sinp, cosp);

    // 3) Flash attention (split-bf16 mma.sync, pre-packed inputs)
    {
        dim3 grid(SEQ / FBQ, NHEAD);
        flash_attn_tc<<<grid, 256, SMEM_FATC>>>(qkvp, att);
    }
    // 4) out = att @ Wproj^T + b  (M=2048, N=1024, K=1024) — tf32 v3
    {
        dim3 grid(DMODEL / 128, SEQ / 128);
        tf32_gemm_nt<<<grid, 256>>>(att, Wproj, bproj, out, DMODEL, DMODEL);
    }
}

// round 17
// speedup vs baseline: 1.3534x; 1.0089x over previous
#include <cuda_runtime.h>
#include <cuda_bf16.h>
#include <cstdint>

#define SEQ    2048
#define DMODEL 1024
#define NHEAD  16
#define HDIM   64
#define QKV_STRIDE (3 * DMODEL)

// Scratch (device-global: no runtime allocation allowed)
__device__ float    g_qkv[SEQ * 3 * DMODEL];    // fp32 q|k|v (GEMM output)
__device__ uint32_t g_qkvp[SEQ * 3 * DMODEL];   // packed bf16x2 (roped q,k + v)
__device__ float    g_att[SEQ * DMODEL];        // attention output [S, DIM]

// ---------------------------------------------------------------------------
// tf32 helpers (GEMM path)
// ---------------------------------------------------------------------------
__device__ __forceinline__ uint32_t f2tf32(float x) {
    uint32_t r;
    asm("cvt.rna.tf32.f32 %0, %1;" : "=r"(r) : "f"(x));
    return r;
}

__device__ __forceinline__ void mma_tf32(float* d, const uint32_t* a,
                                         const uint32_t* b) {
    asm("mma.sync.aligned.m16n8k8.row.col.f32.tf32.tf32.f32 "
        "{%0,%1,%2,%3}, {%4,%5,%6,%7}, {%8,%9}, {%0,%1,%2,%3};"
        : "+f"(d[0]), "+f"(d[1]), "+f"(d[2]), "+f"(d[3])
        : "r"(a[0]), "r"(a[1]), "r"(a[2]), "r"(a[3]),
          "r"(b[0]), "r"(b[1]));
}

// ---------------------------------------------------------------------------
// bf16x2 helpers (flash path): uint32 = (bf16 hi | bf16(x-hi) << 16).
// mma(A=(hi,lo), B=(hi',hi')) + mma(A, B=(lo',lo')) = exact (hi+lo)(hi'+lo').
// ---------------------------------------------------------------------------
__device__ __forceinline__ uint32_t pack_bf16x2(float x) {
    __nv_bfloat16 h = __float2bfloat16(x);
    __nv_bfloat16 l = __float2bfloat16(x - __bfloat162float(h));
    return (uint32_t)__bfloat16_as_ushort(h) |
           ((uint32_t)__bfloat16_as_ushort(l) << 16);
}
__device__ __forceinline__ uint32_t dup_hi(uint32_t x) { return __byte_perm(x, x, 0x1010); }
__device__ __forceinline__ uint32_t dup_lo(uint32_t x) { return __byte_perm(x, x, 0x3232); }

__device__ __forceinline__ void mma_bf16(float* d, const uint32_t* a,
                                         const uint32_t* b) {
    asm("mma.sync.aligned.m16n8k16.row.col.f32.bf16.bf16.f32 "
        "{%0,%1,%2,%3}, {%4,%5,%6,%7}, {%8,%9}, {%0,%1,%2,%3};"
        : "+f"(d[0]), "+f"(d[1]), "+f"(d[2]), "+f"(d[3])
        : "r"(a[0]), "r"(a[1]), "r"(a[2]), "r"(a[3]),
          "r"(b[0]), "r"(b[1]));
}

// Scale a packed (hi,lo) pair by an exact power of two (0.125).
__device__ __forceinline__ uint32_t scale8_packed(uint32_t w) {
    __nv_bfloat162 b = *reinterpret_cast<__nv_bfloat162*>(&w);
    __nv_bfloat162 s = __float2bfloat162_rn(0.125f);
    b = __hmul2(b, s);
    return *reinterpret_cast<uint32_t*>(&b);
}

// cp.async helpers
#define CP_ASYNC16(dst_u32, src_ptr) \
    asm volatile("cp.async.cg.shared.global [%0], [%1], 16;" \
                 :: "r"(dst_u32), "l"(src_ptr) : "memory")
#define CP_COMMIT() asm volatile("cp.async.commit_group;" ::: "memory")
#define CP_WAIT(n)  asm volatile("cp.async.wait_group %0;" :: "n"(n) : "memory")

__device__ __forceinline__ uint32_t smem_u32(const void* p) {
    uint32_t a;
    asm("{ .reg .u64 t; cvta.to.shared.u64 t, %1; cvt.u32.u64 %0, t; }"
        : "=r"(a) : "l"(p));
    return a;
}

// ---------------------------------------------------------------------------
// TF32 tensor-core GEMM v3 (NT): unchanged from R16 (passing).
// ---------------------------------------------------------------------------
__global__ __launch_bounds__(256, 2)
void tf32_gemm_nt(const float* __restrict__ A, const float* __restrict__ B,
                  const float* __restrict__ bias, float* __restrict__ C,
                  int N, int K) {
    constexpr int BM = 128, BN = 128, BK = 16, LD = 20;
    __shared__ __align__(16) uint32_t As[2][BM][LD];
    __shared__ __align__(16) uint32_t Bs[2][BN][LD];

    const int t    = threadIdx.x;
    const int lane = t & 31;
    const int w    = t >> 5;
    const int wm   = w >> 2;
    const int wn   = w & 3;
    const int g    = lane >> 2;
    const int tg   = lane & 3;
    const int bm   = blockIdx.y * BM;
    const int bn   = blockIdx.x * BN;

    const int lr = t >> 1;
    const int lc = (t & 1) * 8;
    const float* Ag = A + (size_t)(bm + lr) * K + lc;
    const float* Bg = B + (size_t)(bn + lr) * K + lc;

    float acc[4][4][4];
#pragma unroll
    for (int mt = 0; mt < 4; mt++)
#pragma unroll
        for (int nt = 0; nt < 4; nt++)
#pragma unroll
            for (int e = 0; e < 4; e++) acc[mt][nt][e] = 0.f;

    const int T = K / BK;
    float4 pa0, pa1, pb0, pb1;

    pa0 = *(const float4*)(Ag);
    pa1 = *(const float4*)(Ag + 4);
    pb0 = *(const float4*)(Bg);
    pb1 = *(const float4*)(Bg + 4);
    As[0][lr][lc + 0] = f2tf32(pa0.x); As[0][lr][lc + 1] = f2tf32(pa0.y);
    As[0][lr][lc + 2] = f2tf32(pa0.z); As[0][lr][lc + 3] = f2tf32(pa0.w);
    As[0][lr][lc + 4] = f2tf32(pa1.x); As[0][lr][lc + 5] = f2tf32(pa1.y);
    As[0][lr][lc + 6] = f2tf32(pa1.z); As[0][lr][lc + 7] = f2tf32(pa1.w);
    Bs[0][lr][lc + 0] = f2tf32(pb0.x); Bs[0][lr][lc + 1] = f2tf32(pb0.y);
    Bs[0][lr][lc + 2] = f2tf32(pb0.z); Bs[0][lr][lc + 3] = f2tf32(pb0.w);
    Bs[0][lr][lc + 4] = f2tf32(pb1.x); Bs[0][lr][lc + 5] = f2tf32(pb1.y);
    Bs[0][lr][lc + 6] = f2tf32(pb1.z); Bs[0][lr][lc + 7] = f2tf32(pb1.w);
    __syncthreads();
    if (T > 1) {
        pa0 = *(const float4*)(Ag + BK);
        pa1 = *(const float4*)(Ag + BK + 4);
        pb0 = *(const float4*)(Bg + BK);
        pb1 = *(const float4*)(Bg + BK + 4);
    }

    for (int tt = 0; tt < T; tt++) {
        const int buf = tt & 1;
#pragma unroll
        for (int ks = 0; ks < BK; ks += 8) {
            uint32_t af[4][4], bf[4][2];
#pragma unroll
            for (int mt = 0; mt < 4; mt++) {
                int row = wm * 64 + mt * 16 + g;
                af[mt][0] = As[buf][row][ks + tg];
                af[mt][1] = As[buf][row + 8][ks + tg];
                af[mt][2] = As[buf][row][ks + tg + 4];
                af[mt][3] = As[buf][row + 8][ks + tg + 4];
            }
#pragma unroll
            for (int nt = 0; nt < 4; nt++) {
                int col = wn * 32 + nt * 8 + g;
                bf[nt][0] = Bs[buf][col][ks + tg];
                bf[nt][1] = Bs[buf][col][ks + tg + 4];
            }
#pragma unroll
            for (int mt = 0; mt < 4; mt++)
#pragma unroll
                for (int nt = 0; nt < 4; nt++)
                    mma_tf32(acc[mt][nt], af[mt], bf[nt]);
        }

        if (tt + 1 < T) {
            const int nb = buf ^ 1;
            As[nb][lr][lc + 0] = f2tf32(pa0.x); As[nb][lr][lc + 1] = f2tf32(pa0.y);
            As[nb][lr][lc + 2] = f2tf32(pa0.z); As[nb][lr][lc + 3] = f2tf32(pa0.w);
            As[nb][lr][lc + 4] = f2tf32(pa1.x); As[nb][lr][lc + 5] = f2tf32(pa1.y);
            As[nb][lr][lc + 6] = f2tf32(pa1.z); As[nb][lr][lc + 7] = f2tf32(pa1.w);
            Bs[nb][lr][lc + 0] = f2tf32(pb0.x); Bs[nb][lr][lc + 1] = f2tf32(pb0.y);
            Bs[nb][lr][lc + 2] = f2tf32(pb0.z); Bs[nb][lr][lc + 3] = f2tf32(pb0.w);
            Bs[nb][lr][lc + 4] = f2tf32(pb1.x); Bs[nb][lr][lc + 5] = f2tf32(pb1.y);
            Bs[nb][lr][lc + 6] = f2tf32(pb1.z); Bs[nb][lr][lc + 7] = f2tf32(pb1.w);
            __syncthreads();
            if (tt + 2 < T) {
                int k0 = (tt + 2) * BK;
                pa0 = *(const float4*)(Ag + k0);
                pa1 = *(const float4*)(Ag + k0 + 4);
                pb0 = *(const float4*)(Bg + k0);
                pb1 = *(const float4*)(Bg + k0 + 4);
            }
        }
    }

#pragma unroll
    for (int nt = 0; nt < 4; nt++) {
        int col = bn + wn * 32 + nt * 8 + tg * 2;
        float b0 = bias[col], b1 = bias[col + 1];
#pragma unroll
        for (int mt = 0; mt < 4; mt++) {
            int row = bm + wm * 64 + mt * 16 + g;
            float2 v0 = make_float2(acc[mt][nt][0] + b0, acc[mt][nt][1] + b1);
            float2 v1 = make_float2(acc[mt][nt][2] + b0, acc[mt][nt][3] + b1);
            *(float2*)(C + (size_t)row * N + col)       = v0;
            *(float2*)(C + (size_t)(row + 8) * N + col) = v1;
        }
    }
}

// ---------------------------------------------------------------------------
// RoPE + pack: reads fp32 g_qkv, writes packed bf16x2 g_qkvp.
// ---------------------------------------------------------------------------
__global__ __launch_bounds__(256)
void rope_pack_kernel(const float* __restrict__ qkv, uint32_t* __restrict__ qkvp,
                      const float* __restrict__ sinp, const float* __restrict__ cosp) {
    int idx = blockIdx.x * blockDim.x + threadIdx.x;
    int d     = idx & 31;
    int h     = (idx >> 5) & (NHEAD - 1);
    int s     = (idx >> 9) & (SEQ - 1);
    int which = idx >> 20;            // 0 = q, 1 = k, 2 = v
    size_t base = (size_t)s * QKV_STRIDE + which * DMODEL + h * HDIM;
    float x1 = qkv[base + d];
    float x2 = qkv[base + d + 32];
    if (which < 2) {
        float cs = cosp[s * HDIM + d];
        float sn = sinp[s * HDIM + d];
        float y1 = x1 * cs - x2 * sn;
        float y2 = x2 * cs + x1 * sn;
        x1 = y1; x2 = y2;
    }
    qkvp[base + d]      = pack_bf16x2(x1);
    qkvp[base + d + 32] = pack_bf16x2(x2);
}

// ---------------------------------------------------------------------------
// Flash attention v4: split-bf16 mma.sync + cp.async double-buffered K/V.
// Per k-tile: commit cp.async for tile kt+1 into the other buffer, then
// compute tile kt — staging latency fully overlapped with mma/softmax.
// Buffer-reuse race is prevented by the top-of-loop __syncthreads (all warps
// done computing the previous tile before new copies target its buffer).
// smem: 2x(K 17.4KB + V 18.4KB) + P 34.8KB = 106.5 KB -> still 2 CTAs/SM.
// ---------------------------------------------------------------------------
constexpr int FBQ = 128;
constexpr int FBK = 64;
constexpr int KLD = 68;
constexpr int VLD = 72;
constexpr int KBUF = FBK * KLD;   // 4352 u32 per K buffer
constexpr int VBUF = FBK * VLD;   // 4608 u32 per V buffer
constexpr int SMEM_FATC =
    (2 * KBUF + 2 * VBUF + FBQ * KLD) * (int)sizeof(uint32_t);  // 106,496 B

__global__ __launch_bounds__(256, 2)
void flash_attn_tc(const uint32_t* __restrict__ qkvp, float* __restrict__ att) {
    extern __shared__ __align__(16) uint32_t su[];
    // su[0 .. 2*KBUF)                : K double buffer
    // su[2*KBUF .. 2*KBUF + 2*VBUF)  : V double buffer
    // su[2*KBUF + 2*VBUF .. ]        : P tile
    uint32_t* Ps = su + 2 * KBUF + 2 * VBUF;

    const int h  = blockIdx.y;
    const int q0 = blockIdx.x * FBQ;
    const int t  = threadIdx.x;
    const int lane = t & 31;
    const int w  = t >> 5;
    const int g  = lane >> 2;
    const int tg = lane & 3;
    const int r0 = w * 16 + g;
    const int r1 = r0 + 8;

    const uint32_t su_base = smem_u32(su);
    const uint32_t* kg = qkvp + DMODEL + h * HDIM;
    const uint32_t* vg = qkvp + 2 * DMODEL + h * HDIM;

    // per-thread staging coordinates (4 copies of 16B per tensor per tile)
    int skey[4], sd4[4];
#pragma unroll
    for (int it = 0; it < 4; it++) {
        int li = it * 256 + t;
        skey[it] = li >> 4;
        sd4[it]  = (li & 15) * 4;
    }

    // ---- issue tile 0 copies, then load Q while they fly --------------------
#pragma unroll
    for (int it = 0; it < 4; it++) {
        size_t goff = (size_t)skey[it] * QKV_STRIDE + sd4[it];
        CP_ASYNC16(su_base + (skey[it] * KLD + sd4[it]) * 4, kg + goff);
        CP_ASYNC16(su_base + (2 * KBUF + skey[it] * VLD + sd4[it]) * 4, vg + goff);
    }
    CP_COMMIT();

    // ---- Q fragments: packed loads + exact /8 scale -------------------------
    uint32_t qa[8][4];
    {
        const uint32_t* qg = qkvp + (size_t)q0 * QKV_STRIDE + h * HDIM;
        const uint32_t* q_r0 = qg + (size_t)r0 * QKV_STRIDE;
        const uint32_t* q_r1 = qg + (size_t)r1 * QKV_STRIDE;
#pragma unroll
        for (int kk = 0; kk < 8; kk++) {
            int c0 = kk * 8 + tg, c1 = c0 + 4;
            qa[kk][0] = scale8_packed(q_r0[c0]);
            qa[kk][1] = scale8_packed(q_r1[c0]);
            qa[kk][2] = scale8_packed(q_r0[c1]);
            qa[kk][3] = scale8_packed(q_r1[c1]);
        }
    }

    float m0 = -1e30f, m1 = -1e30f, l0 = 0.f, l1 = 0.f;
    float oacc[8][4];
#pragma unroll
    for (int nt = 0; nt < 8; nt++)
#pragma unroll
        for (int e = 0; e < 4; e++) oacc[nt][e] = 0.f;

    constexpr int NT = SEQ / FBK;   // 32
    for (int kt = 0; kt < NT; kt++) {
        __syncthreads();   // all warps done with BOTH buffers' previous use
        if (kt + 1 < NT) {
            const int nb = (kt + 1) & 1;
#pragma unroll
            for (int it = 0; it < 4; it++) {
                size_t goff = (size_t)((kt + 1) * FBK + skey[it]) * QKV_STRIDE + sd4[it];
                CP_ASYNC16(su_base + (nb * KBUF + skey[it] * KLD + sd4[it]) * 4,
                           kg + goff);
                CP_ASYNC16(su_base + (2 * KBUF + nb * VBUF + skey[it] * VLD + sd4[it]) * 4,
                           vg + goff);
            }
            CP_COMMIT();
            CP_WAIT(1);    // tile kt complete; tile kt+1 may still fly
        } else {
            CP_WAIT(0);
        }
        __syncthreads();   // tile kt's data visible to all warps

        const uint32_t* Ks = su + (kt & 1) * KBUF;
        const uint32_t* Vs = su + 2 * KBUF + (kt & 1) * VBUF;

        // ---- S = (Q/8) @ K^T (split-bf16) -----------------------------------
        float sacc[8][4];
#pragma unroll
        for (int nt = 0; nt < 8; nt++)
#pragma unroll
            for (int e = 0; e < 4; e++) sacc[nt][e] = 0.f;

#pragma unroll
        for (int kk = 0; kk < 8; kk++) {
            int kc = kk * 8;
#pragma unroll
            for (int nt = 0; nt < 8; nt++) {
                int krow = nt * 8 + g;
                uint32_t b0 = Ks[krow * KLD + kc + tg];
                uint32_t b1 = Ks[krow * KLD + kc + tg + 4];
                uint32_t bhh[2] = {dup_hi(b0), dup_hi(b1)};
                uint32_t bll[2] = {dup_lo(b0), dup_lo(b1)};
                mma_bf16(sacc[nt], qa[kk], bhh);
                mma_bf16(sacc[nt], qa[kk], bll);
            }
        }

        // ---- online softmax -------------------------------------------------
        float mx0 = sacc[0][0], mx1 = sacc[0][2];
#pragma unroll
        for (int nt = 0; nt < 8; nt++) {
            mx0 = fmaxf(mx0, fmaxf(sacc[nt][0], sacc[nt][1]));
            mx1 = fmaxf(mx1, fmaxf(sacc[nt][2], sacc[nt][3]));
        }
        mx0 = fmaxf(mx0, __shfl_xor_sync(0xffffffffu, mx0, 1));
        mx0 = fmaxf(mx0, __shfl_xor_sync(0xffffffffu, mx0, 2));
        mx1 = fmaxf(mx1, __shfl_xor_sync(0xffffffffu, mx1, 1));
        mx1 = fmaxf(mx1, __shfl_xor_sync(0xffffffffu, mx1, 2));

        float nm0 = fmaxf(m0, mx0), nm1 = fmaxf(m1, mx1);
        float a0 = __expf(m0 - nm0), a1 = __expf(m1 - nm1);
        float s0 = 0.f, s1 = 0.f;
#pragma unroll
        for (int nt = 0; nt < 8; nt++) {
            int c = nt * 8 + 2 * tg;
            float p00 = __expf(sacc[nt][0] - nm0);
            float p01 = __expf(sacc[nt][1] - nm0);
            float p10 = __expf(sacc[nt][2] - nm1);
            float p11 = __expf(sacc[nt][3] - nm1);
            s0 += p00 + p01;
            s1 += p10 + p11;
            *(uint2*)(Ps + r0 * KLD + c) =
                make_uint2(pack_bf16x2(p00), pack_bf16x2(p01));
            *(uint2*)(Ps + r1 * KLD + c) =
                make_uint2(pack_bf16x2(p10), pack_bf16x2(p11));
        }
        s0 += __shfl_xor_sync(0xffffffffu, s0, 1);
        s0 += __shfl_xor_sync(0xffffffffu, s0, 2);
        s1 += __shfl_xor_sync(0xffffffffu, s1, 1);
        s1 += __shfl_xor_sync(0xffffffffu, s1, 2);
        l0 = l0 * a0 + s0;
        l1 = l1 * a1 + s1;
        m0 = nm0; m1 = nm1;
#pragma unroll
        for (int nt = 0; nt < 8; nt++) {
            oacc[nt][0] *= a0; oacc[nt][1] *= a0;
            oacc[nt][2] *= a1; oacc[nt][3] *= a1;
        }
        __syncwarp();   // P region is per-warp-private

        // ---- O += P @ V (split-bf16) ----------------------------------------
#pragma unroll
        for (int kk = 0; kk < 8; kk++) {
            int kc = kk * 8;
            uint32_t pa[4];
            pa[0] = Ps[r0 * KLD + kc + tg];
            pa[1] = Ps[r1 * KLD + kc + tg];
            pa[2] = Ps[r0 * KLD + kc + tg + 4];
            pa[3] = Ps[r1 * KLD + kc + tg + 4];
#pragma unroll
            for (int nt = 0; nt < 8; nt++) {
                int dcol = nt * 8 + g;
                uint32_t v0 = Vs[(kc + tg) * VLD + dcol];
                uint32_t v1 = Vs[(kc + tg + 4) * VLD + dcol];
                uint32_t bhh[2] = {dup_hi(v0), dup_hi(v1)};
                uint32_t bll[2] = {dup_lo(v0), dup_lo(v1)};
                mma_bf16(oacc[nt], pa, bhh);
                mma_bf16(oacc[nt], pa, bll);
            }
        }
    }

    float inv0 = 1.f / l0, inv1 = 1.f / l1;
#pragma unroll
    for (int nt = 0; nt < 8; nt++) {
        int col = h * HDIM + nt * 8 + 2 * tg;
        *(float2*)(att + (size_t)(q0 + r0) * DMODEL + col) =
            make_float2(oacc[nt][0] * inv0, oacc[nt][1] * inv0);
        *(float2*)(att + (size_t)(q0 + r1) * DMODEL + col) =
            make_float2(oacc[nt][2] * inv1, oacc[nt][3] * inv1);
    }
}

// ---------------------------------------------------------------------------
extern "C" void kernel_launch(void* const* d_in, const int* in_sizes, int n_in,
                              void* d_out, int out_size) {
    const float* x     = (const float*)d_in[0];
    const float* sinp  = (const float*)d_in[1];
    const float* cosp  = (const float*)d_in[2];
    const float* Wqkv  = (const float*)d_in[3];
    const float* bqkv  = (const float*)d_in[4];
    const float* Wproj = (const float*)d_in[5];
    const float* bproj = (const float*)d_in[6];
    float* out = (float*)d_out;

    float* qkv = nullptr;
    uint32_t* qkvp = nullptr;
    float* att = nullptr;
    cudaGetSymbolAddress((void**)&qkv, g_qkv);
    cudaGetSymbolAddress((void**)&qkvp, g_qkvp);
    cudaGetSymbolAddress((void**)&att, g_att);

    cudaFuncSetAttribute(flash_attn_tc, cudaFuncAttributeMaxDynamicSharedMemorySize,
                         SMEM_FATC);

    // 1) QKV = x @ Wqkv^T + b  (M=2048, N=3072, K=1024)
    {
        dim3 grid(3072 / 128, SEQ / 128);
        tf32_gemm_nt<<<grid, 256>>>(x, Wqkv, bqkv, qkv, 3072, DMODEL);
    }
    // 2) RoPE q,k + pack q,k,v
    rope_pack_kernel<<<(3 * SEQ * NHEAD * 32) / 256, 256>>>(qkv, qkvp, sinp, cosp);

    // 3) Flash attention (split-bf16 mma.sync, cp.async double-buffered)
    {
        dim3 grid(SEQ / FBQ, NHEAD);
        flash_attn_tc<<<grid, 256, SMEM_FATC>>>(qkvp, att);
    }
    // 4) out = att @ Wproj^T + b  (M=2048, N=1024, K=1024)
    {
        dim3 grid(DMODEL / 128, SEQ / 128);
        tf32_gemm_nt<<<grid, 256>>>(att, Wproj, bproj, out, DMODEL, DMODEL);
    }
}